// round 14
// baseline (speedup 1.0000x reference)
#include <cuda_runtime.h>
#include <cuda_fp16.h>
#include <cuda_bf16.h>
#include <cstdint>

#define N_NODES_MAX 50000
#define D 64

// Per-node record, 256 B:
//   halves [0..63]   = G = feat@W1 (fp16), natural column order
//   halves [64..127] = feat (fp16), PERMUTED: pos 64+8q+j holds
//                      feat[4q+j] for j<4, feat[32+4q+(j-4)] for j>=4
__device__ __half g_rec[N_NODES_MAX * 128];
__device__ int g_idx_is64;

// Barrier + work-stealing state (self-resetting at kernel exit).
__device__ unsigned g_bar_cnt = 0;
__device__ unsigned g_exit_cnt = 0;
__device__ unsigned g_ecur[8] = {0, 0, 0, 0, 0, 0, 0, 0};

#define SA_STRIDE 66    // halves; conflict-free A frags
#define SG_STRIDE 72    // halves; 144B row, 16B-aligned flush
#define CHUNK_PAIRS 16  // pairs of edges per warp steal (32 edges)

// ---------------------------------------------------------------------------
// Fused kernel.
// Phase 1: 128-node tiles, ALL 8 warps HMMA (validated R11); <=1 tile/block.
// Grid barrier (grid sized by occupancy on host -> all blocks co-resident).
// Phase 2: edge compute with warp-level work stealing from 8 striped cursors
//          (kills the persistent-kernel tail spread).
// ---------------------------------------------------------------------------
__global__ void __launch_bounds__(256, 4)
fused_kernel(const float* __restrict__ feat,
             const void* __restrict__ src_idx,
             const void* __restrict__ dst_idx,
             const float* __restrict__ W1,
             const float* __restrict__ b1,
             const float* __restrict__ W2,
             const float* __restrict__ b2,
             float* __restrict__ out,
             int n_nodes, int n_edges) {
    __shared__ uint32_t Bf[4][8][32][2];           // 8 KB
    __shared__ __half sA[128 * SA_STRIDE];         // 16.9 KB
    __shared__ __half sG[128 * SG_STRIDE];         // 18 KB

    const int tid = threadIdx.x;
    const int w = tid >> 5;          // warp 0..7
    const int lane = tid & 31;
    const int g = lane >> 2;
    const int tig = lane & 3;

    // ---------------- Phase 1: node GEMM ----------------
    if (blockIdx.x == 0 && tid == 0) {
        int is64 = 1;
        int m = n_edges < 16 ? n_edges : 16;
        for (int i = 0; i < m; i++) {
            long long v = ((const long long*)src_idx)[i];
            if (v < 0 || v >= (long long)n_nodes) { is64 = 0; break; }
        }
        g_idx_is64 = is64;
    }

    if (w < 4) {   // B fragments: warps 0-3 build k-tile = w
        int k0 = w * 16 + 2 * tig;
#pragma unroll
        for (int nt = 0; nt < 8; nt++) {
            int n = nt * 8 + g;
            __half2 b01 = __floats2half2_rn(W1[k0 * 64 + n], W1[(k0 + 1) * 64 + n]);
            __half2 b23 = __floats2half2_rn(W1[(k0 + 8) * 64 + n], W1[(k0 + 9) * 64 + n]);
            Bf[w][nt][lane][0] = *(uint32_t*)&b01;
            Bf[w][nt][lane][1] = *(uint32_t*)&b23;
        }
    }
    __syncthreads();

    const int n_tiles = (n_nodes + 127) >> 7;       // 391
    for (int t = blockIdx.x; t < n_tiles; t += gridDim.x) {
        const int base = t * 128;
        const int rows = min(128, n_nodes - base);

#pragma unroll
        for (int p = 0; p < 8; p++) {
            int flat = p * 256 + tid;               // 128 rows x 16 float4
            int node = flat >> 4;
            int c = flat & 15;
            float4 f;
            if (node < rows) f = __ldg(&((const float4*)feat)[(long long)(base + node) * 16 + c]);
            else             f = make_float4(0.f, 0.f, 0.f, 0.f);
            __half2 h01 = __floats2half2_rn(f.x, f.y);
            __half2 h23 = __floats2half2_rn(f.z, f.w);
            __half* dstp = &sA[node * SA_STRIDE + c * 4];
            *(__half2*)(dstp)     = h01;
            *(__half2*)(dstp + 2) = h23;
        }
        __syncthreads();

        {   // MMA: all 8 warps; warp w -> rows 16w..16w+15
            int r0 = w * 16 + g;
            int r1 = r0 + 8;
            uint32_t a[4][4];
#pragma unroll
            for (int kt = 0; kt < 4; kt++) {
                int col = kt * 16 + 2 * tig;
                a[kt][0] = *(uint32_t*)&sA[r0 * SA_STRIDE + col];
                a[kt][1] = *(uint32_t*)&sA[r1 * SA_STRIDE + col];
                a[kt][2] = *(uint32_t*)&sA[r0 * SA_STRIDE + col + 8];
                a[kt][3] = *(uint32_t*)&sA[r1 * SA_STRIDE + col + 8];
            }
#pragma unroll
            for (int nt = 0; nt < 8; nt++) {
                float d0 = 0.f, d1 = 0.f, d2 = 0.f, d3 = 0.f;
#pragma unroll
                for (int kt = 0; kt < 4; kt++) {
                    asm volatile(
                        "mma.sync.aligned.m16n8k16.row.col.f32.f16.f16.f32 "
                        "{%0,%1,%2,%3}, {%4,%5,%6,%7}, {%8,%9}, {%0,%1,%2,%3};"
                        : "+f"(d0), "+f"(d1), "+f"(d2), "+f"(d3)
                        : "r"(a[kt][0]), "r"(a[kt][1]), "r"(a[kt][2]), "r"(a[kt][3]),
                          "r"(Bf[kt][nt][lane][0]), "r"(Bf[kt][nt][lane][1]));
                }
                int cc = nt * 8 + 2 * tig;
                *(__half2*)&sG[r0 * SG_STRIDE + cc] = __floats2half2_rn(d0, d1);
                *(__half2*)&sG[r1 * SG_STRIDE + cc] = __floats2half2_rn(d2, d3);
            }
        }

        {   // permuted F half: sA -> gmem (node = tid/2, hf = tid&1)
            int node = tid >> 1;
            int hf = tid & 1;
            if (node < rows) {
                const __half* srow = &sA[node * SA_STRIDE + (hf ? 32 : 0)];
                __half* drow = &g_rec[(long long)(base + node) * 128 + 64 + (hf ? 4 : 0)];
#pragma unroll
                for (int q = 0; q < 8; q++) {
                    uint2 u;
                    u.x = *(const uint32_t*)&srow[4 * q];
                    u.y = *(const uint32_t*)&srow[4 * q + 2];
                    *(uint2*)&drow[8 * q] = u;
                }
            }
        }
        __syncthreads();

#pragma unroll
        for (int p = 0; p < 4; p++) {   // flush G -> g_rec, coalesced uint4
            int flat = p * 256 + tid;               // 128 nodes x 8 uint4
            int node = flat >> 3;
            int c = flat & 7;
            if (node < rows) {
                uint4 v = *(const uint4*)&sG[node * SG_STRIDE + c * 8];
                ((uint4*)g_rec)[(long long)(base + node) * 16 + c] = v;
            }
        }
        __syncthreads();
    }

    // Preload edge-phase params (overlaps the barrier wait).
    const int l = tid & 7;
    float4 b1a = __ldg(&((const float4*)b1)[2 * l]);
    float4 b1b = __ldg(&((const float4*)b1)[2 * l + 1]);
    float4 w2a = __ldg(&((const float4*)W2)[2 * l]);
    float4 w2b = __ldg(&((const float4*)W2)[2 * l + 1]);
    float b2v = __ldg(&b2[0]);

    // ---------------- Grid barrier ----------------
    __syncthreads();
    if (tid == 0) {
        __threadfence();                       // publish g_rec / g_idx_is64
        atomicAdd(&g_bar_cnt, 1u);
        while (*(volatile unsigned*)&g_bar_cnt < gridDim.x) { }
    }
    __syncthreads();
    __threadfence();                           // acquire

    // ---------------- Phase 2: edge compute (warp work-stealing) ----------
    {
        const int giw = (lane >> 3);           // group in warp 0..3
        const int NP = (n_edges + 1) >> 1;     // edge pairs
        const int wgid = (int)blockIdx.x * 8 + w;
        const int stripe = wgid & 7;
        const int lo = (int)(((long long)stripe * NP) >> 3);
        const int hi = (int)(((long long)(stripe + 1) * NP) >> 3);
        const unsigned nchunk = (unsigned)((hi - lo + CHUNK_PAIRS - 1) / CHUNK_PAIRS);

        const int is64 = g_idx_is64;
        const uint4* R16 = (const uint4*)g_rec;
        float4* O4 = (float4*)out;

        for (;;) {
            unsigned c = 0;
            if (lane == 0) c = atomicAdd(&g_ecur[stripe], 1u);
            c = __shfl_sync(0xffffffffu, c, 0);
            if (c >= nchunk) break;
            int pBase = lo + (int)c * CHUNK_PAIRS + giw * 4;

#pragma unroll
            for (int i = 0; i < 4; i++) {
                int pair = pBase + i;
                if (pair >= hi) break;
                int e0 = pair * 2;
                int e1 = e0 + 1;
                bool hasB = (e1 < n_edges);

                long long sA_, dA_, sB_ = 0, dB_ = 0;
                if (is64) {
                    longlong2 sp = __ldg(&((const longlong2*)src_idx)[pair]);
                    longlong2 dp = __ldg(&((const longlong2*)dst_idx)[pair]);
                    sA_ = sp.x; dA_ = dp.x; sB_ = sp.y; dB_ = dp.y;
                } else {
                    int2 sp = __ldg(&((const int2*)src_idx)[pair]);
                    int2 dp = __ldg(&((const int2*)dst_idx)[pair]);
                    sA_ = sp.x; dA_ = dp.x; sB_ = sp.y; dB_ = dp.y;
                }

                uint4 gsA = __ldg(&R16[sA_ * 16 + l]);
                uint4 gdA = __ldg(&R16[dA_ * 16 + l]);
                uint4 fdA = __ldg(&R16[dA_ * 16 + 8 + l]);
                uint4 gsB, gdB, fdB;
                if (hasB) {
                    gsB = __ldg(&R16[sB_ * 16 + l]);
                    gdB = __ldg(&R16[dB_ * 16 + l]);
                    fdB = __ldg(&R16[dB_ * 16 + 8 + l]);
                }

#define EDGE_BODY(GS, GD, FD, EIDX)                                            \
                {                                                              \
                    float2 s0 = __half22float2(*(const __half2*)&GS.x);        \
                    float2 s1 = __half22float2(*(const __half2*)&GS.y);        \
                    float2 s2 = __half22float2(*(const __half2*)&GS.z);        \
                    float2 s3 = __half22float2(*(const __half2*)&GS.w);        \
                    float2 dd0 = __half22float2(*(const __half2*)&GD.x);       \
                    float2 dd1 = __half22float2(*(const __half2*)&GD.y);       \
                    float2 dd2 = __half22float2(*(const __half2*)&GD.z);       \
                    float2 dd3 = __half22float2(*(const __half2*)&GD.w);       \
                    float h0 = fmaxf(s0.x - dd0.x + b1a.x, 0.f);               \
                    float h1 = fmaxf(s0.y - dd0.y + b1a.y, 0.f);               \
                    float h2 = fmaxf(s1.x - dd1.x + b1a.z, 0.f);               \
                    float h3 = fmaxf(s1.y - dd1.y + b1a.w, 0.f);               \
                    float h4 = fmaxf(s2.x - dd2.x + b1b.x, 0.f);               \
                    float h5 = fmaxf(s2.y - dd2.y + b1b.y, 0.f);               \
                    float h6 = fmaxf(s3.x - dd3.x + b1b.z, 0.f);               \
                    float h7 = fmaxf(s3.y - dd3.y + b1b.w, 0.f);               \
                    float p = h0 * w2a.x;                                      \
                    p = fmaf(h1, w2a.y, p); p = fmaf(h2, w2a.z, p);            \
                    p = fmaf(h3, w2a.w, p); p = fmaf(h4, w2b.x, p);            \
                    p = fmaf(h5, w2b.y, p); p = fmaf(h6, w2b.z, p);            \
                    p = fmaf(h7, w2b.w, p);                                    \
                    p += __shfl_xor_sync(0xffffffffu, p, 1, 8);                \
                    p += __shfl_xor_sync(0xffffffffu, p, 2, 8);                \
                    p += __shfl_xor_sync(0xffffffffu, p, 4, 8);                \
                    float aa = __expf(-fmaxf(p + b2v, 0.f));                   \
                    float2 f0 = __half22float2(*(const __half2*)&FD.x);        \
                    float2 f1 = __half22float2(*(const __half2*)&FD.y);        \
                    float2 f2 = __half22float2(*(const __half2*)&FD.z);        \
                    float2 f3 = __half22float2(*(const __half2*)&FD.w);        \
                    float4 oA = make_float4(aa * f0.x, aa * f0.y, aa * f1.x, aa * f1.y); \
                    float4 oB = make_float4(aa * f2.x, aa * f2.y, aa * f3.x, aa * f3.y); \
                    long long ob = (long long)(EIDX) * 16;                     \
                    O4[ob + l] = oA;                                           \
                    O4[ob + l + 8] = oB;                                       \
                }

                EDGE_BODY(gsA, gdA, fdA, e0)
                if (hasB) EDGE_BODY(gsB, gdB, fdB, e1)
#undef EDGE_BODY
            }
        }
    }

    // ---------------- Exit: last block resets all counters ----------------
    __syncthreads();
    if (tid == 0) {
        unsigned v = atomicAdd(&g_exit_cnt, 1u);
        if (v == gridDim.x - 1u) {
            g_bar_cnt = 0u;
            g_exit_cnt = 0u;
#pragma unroll
            for (int s = 0; s < 8; s++) g_ecur[s] = 0u;
            __threadfence();
        }
    }
}

// ---------------------------------------------------------------------------
// kernel_launch — inputs (metadata order):
//   0 features [50000,64] f32
//   1 src_idx  [800000]   int64 (or int32, detected)
//   2 dst_idx  [800000]   int64/int32
//   3 W1 [64,64] f32   4 b1 [64] f32   5 W2 [64,1] f32   6 b2 [1] f32
// output: [800000, 64] f32
//
// Grid = occupancy-query resident blocks (deadlock-proof for the barrier).
// ---------------------------------------------------------------------------
extern "C" void kernel_launch(void* const* d_in, const int* in_sizes, int n_in,
                              void* d_out, int out_size) {
    const float* feat = (const float*)d_in[0];
    const void*  src  = d_in[1];
    const void*  dst  = d_in[2];
    const float* W1   = (const float*)d_in[3];
    const float* b1   = (const float*)d_in[4];
    const float* W2   = (const float*)d_in[5];
    const float* b2   = (const float*)d_in[6];
    float* out = (float*)d_out;

    int n_nodes = in_sizes[0] / D;
    int n_edges = in_sizes[1];

    int dev = 0;
    cudaGetDevice(&dev);
    int sms = 148;
    cudaDeviceGetAttribute(&sms, cudaDevAttrMultiProcessorCount, dev);
    int maxb = 1;
    cudaOccupancyMaxActiveBlocksPerMultiprocessor(&maxb, fused_kernel, 256, 0);
    if (maxb < 1) maxb = 1;
    int grid = sms * maxb;
    if (grid > 1024) grid = 1024;

    fused_kernel<<<grid, 256>>>(feat, src, dst, W1, b1, W2, b2, out,
                                n_nodes, n_edges);
}

// round 15
// speedup vs baseline: 1.0423x; 1.0423x over previous
#include <cuda_runtime.h>
#include <cuda_fp16.h>
#include <cuda_bf16.h>
#include <cstdint>

#define N_NODES_MAX 50000
#define D 64

// Per-node record, 256 B:
//   halves [0..63]   = G = feat@W1 (fp16), natural column order
//   halves [64..127] = feat (fp16), PERMUTED: pos 64+8q+j holds
//                      feat[4q+j] for j<4, feat[32+4q+(j-4)] for j>=4
// Edge-lane l reads G cols [8l..8l+8) and its 8 feat cols each as ONE uint4.
__device__ __half g_rec[N_NODES_MAX * 128];
__device__ int g_idx_is64;

#define SA_STRIDE 66    // halves; conflict-free A frags
#define SG_STRIDE 72    // halves; 144B row, 16B-aligned flush

// ---------------------------------------------------------------------------
// Node GEMM: 256 threads, 128-node tile, ALL 8 warps HMMA (mapping validated
// across R8-R14). 391 blocks, one tile each, single wave.
// ---------------------------------------------------------------------------
__global__ void __launch_bounds__(256)
node_gemm_kernel(const float* __restrict__ feat,
                 const float* __restrict__ W1,
                 int n_nodes,
                 const long long* __restrict__ src_probe,
                 int n_edges) {
    __shared__ uint32_t Bf[4][8][32][2];           // 8 KB
    __shared__ __half sA[128 * SA_STRIDE];         // 16.9 KB
    __shared__ __half sG[128 * SG_STRIDE];         // 18 KB

    const int tid = threadIdx.x;
    const int w = tid >> 5;          // warp 0..7
    const int lane = tid & 31;
    const int g = lane >> 2;
    const int tig = lane & 3;

    if (blockIdx.x == 0 && tid == 0) {
        int is64 = 1;
        int m = n_edges < 16 ? n_edges : 16;
        for (int i = 0; i < m; i++) {
            long long v = src_probe[i];
            if (v < 0 || v >= (long long)n_nodes) { is64 = 0; break; }
        }
        g_idx_is64 = is64;
    }

    // B fragments: warps 0-3 build k-tile = w:
    //   b0=(k=2tig,n) b1=(k+1) b2=(k+8) b3=(k+9), n = nt*8+g
    if (w < 4) {
        int k0 = w * 16 + 2 * tig;
#pragma unroll
        for (int nt = 0; nt < 8; nt++) {
            int n = nt * 8 + g;
            __half2 b01 = __floats2half2_rn(W1[k0 * 64 + n], W1[(k0 + 1) * 64 + n]);
            __half2 b23 = __floats2half2_rn(W1[(k0 + 8) * 64 + n], W1[(k0 + 9) * 64 + n]);
            Bf[w][nt][lane][0] = *(uint32_t*)&b01;
            Bf[w][nt][lane][1] = *(uint32_t*)&b23;
        }
    }

    const int n_tiles = (n_nodes + 127) >> 7;       // 391
    for (int t = blockIdx.x; t < n_tiles; t += gridDim.x) {
        const int base = t * 128;
        const int rows = min(128, n_nodes - base);

        // load feat tile (zero-pad), coalesced float4 -> fp16 sA
#pragma unroll
        for (int p = 0; p < 8; p++) {
            int flat = p * 256 + tid;               // 128 rows x 16 float4
            int node = flat >> 4;
            int c = flat & 15;
            float4 f;
            if (node < rows) f = __ldg(&((const float4*)feat)[(long long)(base + node) * 16 + c]);
            else             f = make_float4(0.f, 0.f, 0.f, 0.f);
            __half2 h01 = __floats2half2_rn(f.x, f.y);
            __half2 h23 = __floats2half2_rn(f.z, f.w);
            __half* dstp = &sA[node * SA_STRIDE + c * 4];
            *(__half2*)(dstp)     = h01;
            *(__half2*)(dstp + 2) = h23;
        }
        __syncthreads();   // sA ready (also orders Bf on first iteration)

        // MMA: all 8 warps; warp w computes rows 16w .. 16w+15
        {
            int r0 = w * 16 + g;
            int r1 = r0 + 8;
            uint32_t a[4][4];
#pragma unroll
            for (int kt = 0; kt < 4; kt++) {
                int col = kt * 16 + 2 * tig;
                a[kt][0] = *(uint32_t*)&sA[r0 * SA_STRIDE + col];
                a[kt][1] = *(uint32_t*)&sA[r1 * SA_STRIDE + col];
                a[kt][2] = *(uint32_t*)&sA[r0 * SA_STRIDE + col + 8];
                a[kt][3] = *(uint32_t*)&sA[r1 * SA_STRIDE + col + 8];
            }
#pragma unroll
            for (int nt = 0; nt < 8; nt++) {
                float d0 = 0.f, d1 = 0.f, d2 = 0.f, d3 = 0.f;
#pragma unroll
                for (int kt = 0; kt < 4; kt++) {
                    asm volatile(
                        "mma.sync.aligned.m16n8k16.row.col.f32.f16.f16.f32 "
                        "{%0,%1,%2,%3}, {%4,%5,%6,%7}, {%8,%9}, {%0,%1,%2,%3};"
                        : "+f"(d0), "+f"(d1), "+f"(d2), "+f"(d3)
                        : "r"(a[kt][0]), "r"(a[kt][1]), "r"(a[kt][2]), "r"(a[kt][3]),
                          "r"(Bf[kt][nt][lane][0]), "r"(Bf[kt][nt][lane][1]));
                }
                int cc = nt * 8 + 2 * tig;
                *(__half2*)&sG[r0 * SG_STRIDE + cc] = __floats2half2_rn(d0, d1);
                *(__half2*)&sG[r1 * SG_STRIDE + cc] = __floats2half2_rn(d2, d3);
            }
        }

        // permuted F half: sA -> gmem directly (node = tid/2, hf = tid&1)
        {
            int node = tid >> 1;
            int hf = tid & 1;
            if (node < rows) {
                const __half* srow = &sA[node * SA_STRIDE + (hf ? 32 : 0)];
                __half* drow = &g_rec[(long long)(base + node) * 128 + 64 + (hf ? 4 : 0)];
#pragma unroll
                for (int q = 0; q < 8; q++) {
                    uint2 u;
                    u.x = *(const uint32_t*)&srow[4 * q];
                    u.y = *(const uint32_t*)&srow[4 * q + 2];
                    *(uint2*)&drow[8 * q] = u;
                }
            }
        }
        __syncthreads();   // sG complete

        // flush G region -> g_rec, coalesced uint4 (first 128 B of each record)
#pragma unroll
        for (int p = 0; p < 4; p++) {
            int flat = p * 256 + tid;               // 128 nodes x 8 uint4
            int node = flat >> 3;
            int c = flat & 7;
            if (node < rows) {
                uint4 v = *(const uint4*)&sG[node * SG_STRIDE + c * 8];
                ((uint4*)g_rec)[(long long)(base + node) * 16 + c] = v;
            }
        }
        __syncthreads();   // protect sA/sG if another tile follows
    }

    cudaTriggerProgrammaticLaunchCompletion();
}

// ---------------------------------------------------------------------------
// Edge kernel (unchanged — at the LTS roofline), PDL-launched.
// ---------------------------------------------------------------------------
__global__ void __launch_bounds__(256, 4)
edge_kernel(const void* __restrict__ src_idx,
            const void* __restrict__ dst_idx,
            const float* __restrict__ b1,
            const float* __restrict__ W2,
            const float* __restrict__ b2,
            float* __restrict__ out,
            int n_edges) {
    const int l = threadIdx.x & 7;
    const int groupInBlock = threadIdx.x >> 3;
    const int gid = (int)blockIdx.x * 32 + groupInBlock;
    const int totalGroups = (int)gridDim.x * 32;

    // Independent preamble — overlaps the gemm kernel's tail under PDL.
    const float4* B14 = (const float4*)b1;
    const float4* W24 = (const float4*)W2;
    float4 b1a = __ldg(&B14[2 * l]);
    float4 b1b = __ldg(&B14[2 * l + 1]);
    float4 w2a = __ldg(&W24[2 * l]);
    float4 w2b = __ldg(&W24[2 * l + 1]);
    float b2v = __ldg(&b2[0]);

    cudaGridDependencySynchronize();

    const int is64 = g_idx_is64;
    const uint4* R16 = (const uint4*)g_rec;
    float4* O4 = (float4*)out;

    for (int e0 = 2 * gid; e0 < n_edges; e0 += 2 * totalGroups) {
        int e1 = e0 + 1;
        bool hasB = (e1 < n_edges);

        long long sA, dA, sB = 0, dB = 0;
        if (is64) {
            longlong2 sp = __ldg(&((const longlong2*)src_idx)[e0 >> 1]);
            longlong2 dp = __ldg(&((const longlong2*)dst_idx)[e0 >> 1]);
            sA = sp.x; dA = dp.x; sB = sp.y; dB = dp.y;
        } else {
            int2 sp = __ldg(&((const int2*)src_idx)[e0 >> 1]);
            int2 dp = __ldg(&((const int2*)dst_idx)[e0 >> 1]);
            sA = sp.x; dA = dp.x; sB = sp.y; dB = dp.y;
        }

        uint4 gsA = __ldg(&R16[sA * 16 + l]);
        uint4 gdA = __ldg(&R16[dA * 16 + l]);
        uint4 fdA = __ldg(&R16[dA * 16 + 8 + l]);
        uint4 gsB, gdB, fdB;
        if (hasB) {
            gsB = __ldg(&R16[sB * 16 + l]);
            gdB = __ldg(&R16[dB * 16 + l]);
            fdB = __ldg(&R16[dB * 16 + 8 + l]);
        }

#define EDGE_BODY(GS, GD, FD, EIDX)                                            \
        {                                                                      \
            float2 s0 = __half22float2(*(const __half2*)&GS.x);                \
            float2 s1 = __half22float2(*(const __half2*)&GS.y);                \
            float2 s2 = __half22float2(*(const __half2*)&GS.z);                \
            float2 s3 = __half22float2(*(const __half2*)&GS.w);                \
            float2 dd0 = __half22float2(*(const __half2*)&GD.x);               \
            float2 dd1 = __half22float2(*(const __half2*)&GD.y);               \
            float2 dd2 = __half22float2(*(const __half2*)&GD.z);               \
            float2 dd3 = __half22float2(*(const __half2*)&GD.w);               \
            float h0 = fmaxf(s0.x - dd0.x + b1a.x, 0.f);                       \
            float h1 = fmaxf(s0.y - dd0.y + b1a.y, 0.f);                       \
            float h2 = fmaxf(s1.x - dd1.x + b1a.z, 0.f);                       \
            float h3 = fmaxf(s1.y - dd1.y + b1a.w, 0.f);                       \
            float h4 = fmaxf(s2.x - dd2.x + b1b.x, 0.f);                       \
            float h5 = fmaxf(s2.y - dd2.y + b1b.y, 0.f);                       \
            float h6 = fmaxf(s3.x - dd3.x + b1b.z, 0.f);                       \
            float h7 = fmaxf(s3.y - dd3.y + b1b.w, 0.f);                       \
            float p = h0 * w2a.x;                                              \
            p = fmaf(h1, w2a.y, p); p = fmaf(h2, w2a.z, p);                    \
            p = fmaf(h3, w2a.w, p); p = fmaf(h4, w2b.x, p);                    \
            p = fmaf(h5, w2b.y, p); p = fmaf(h6, w2b.z, p);                    \
            p = fmaf(h7, w2b.w, p);                                            \
            p += __shfl_xor_sync(0xffffffffu, p, 1, 8);                        \
            p += __shfl_xor_sync(0xffffffffu, p, 2, 8);                        \
            p += __shfl_xor_sync(0xffffffffu, p, 4, 8);                        \
            float aa = __expf(-fmaxf(p + b2v, 0.f));                           \
            float2 f0 = __half22float2(*(const __half2*)&FD.x);                \
            float2 f1 = __half22float2(*(const __half2*)&FD.y);                \
            float2 f2 = __half22float2(*(const __half2*)&FD.z);                \
            float2 f3 = __half22float2(*(const __half2*)&FD.w);                \
            float4 oA = make_float4(aa * f0.x, aa * f0.y, aa * f1.x, aa * f1.y); \
            float4 oB = make_float4(aa * f2.x, aa * f2.y, aa * f3.x, aa * f3.y); \
            long long ob = (long long)(EIDX) * 16;                             \
            O4[ob + l] = oA;                                                   \
            O4[ob + l + 8] = oB;                                               \
        }

        EDGE_BODY(gsA, gdA, fdA, e0)
        if (hasB) EDGE_BODY(gsB, gdB, fdB, e1)
#undef EDGE_BODY
    }
}

// ---------------------------------------------------------------------------
// kernel_launch — inputs (metadata order):
//   0 features [50000,64] f32
//   1 src_idx  [800000]   int64 (or int32, detected)
//   2 dst_idx  [800000]   int64/int32
//   3 W1 [64,64] f32   4 b1 [64] f32   5 W2 [64,1] f32   6 b2 [1] f32
// output: [800000, 64] f32
// ---------------------------------------------------------------------------
extern "C" void kernel_launch(void* const* d_in, const int* in_sizes, int n_in,
                              void* d_out, int out_size) {
    const float* feat = (const float*)d_in[0];
    const void*  src  = d_in[1];
    const void*  dst  = d_in[2];
    const float* W1   = (const float*)d_in[3];
    const float* b1   = (const float*)d_in[4];
    const float* W2   = (const float*)d_in[5];
    const float* b2   = (const float*)d_in[6];
    float* out = (float*)d_out;

    int n_nodes = in_sizes[0] / D;
    int n_edges = in_sizes[1];

    int n_tiles = (n_nodes + 127) / 128;         // 391, one tile per block
    node_gemm_kernel<<<n_tiles, 256>>>(feat, W1, n_nodes,
                                       (const long long*)src, n_edges);

    cudaLaunchConfig_t cfg = {};
    cfg.gridDim = dim3(1184, 1, 1);
    cfg.blockDim = dim3(256, 1, 1);
    cfg.dynamicSmemBytes = 0;
    cfg.stream = 0;
    cudaLaunchAttribute attrs[1];
    attrs[0].id = cudaLaunchAttributeProgrammaticStreamSerialization;
    attrs[0].val.programmaticStreamSerializationAllowed = 1;
    cfg.attrs = attrs;
    cfg.numAttrs = 1;
    cudaLaunchKernelEx(&cfg, edge_kernel, src, dst, b1, W2, b2, out, n_edges);
}

// round 16
// speedup vs baseline: 1.0631x; 1.0199x over previous
#include <cuda_runtime.h>
#include <cuda_fp16.h>
#include <cuda_bf16.h>
#include <cstdint>

#define N_NODES_MAX 50000
#define D 64

// Per-node record, 256 B:
//   halves [0..63]   = G = feat@W1 (fp16), natural column order
//   halves [64..127] = feat (fp16), PERMUTED: pos 64+8q+j holds
//                      feat[4q+j] for j<4, feat[32+4q+(j-4)] for j>=4
// Edge-lane l reads G cols [8l..8l+8) and its 8 feat cols each as ONE uint4.
__device__ __half g_rec[N_NODES_MAX * 128];
__device__ int g_idx_is64;

#define SA_STRIDE 66    // halves; conflict-free A frags
#define SR_STRIDE 136   // halves; conflict-free D writes, 16B-aligned flush

// ---------------------------------------------------------------------------
// Node GEMM via tensor cores, fully smem-staged (exact R9 champion config):
//   - 64-node tile of feat loaded ONCE, coalesced, converted to fp16 in sA
//   - m16n8k16 HMMA per warp (4 warps), D frags into padded sRec
//   - permuted F half built smem->smem from sA
//   - sRec flushed to g_rec with coalesced uint4 stores (full 128B lines)
// ---------------------------------------------------------------------------
__global__ void __launch_bounds__(128)
node_gemm_kernel(const float* __restrict__ feat,
                 const float* __restrict__ W1,
                 int n_nodes,
                 const long long* __restrict__ src_probe,
                 int n_edges) {
    __shared__ uint32_t Bf[4][8][32][2];           // 8 KB B fragments
    __shared__ __half sA[64 * SA_STRIDE];          // 8.25 KB fp16 feat tile
    __shared__ __half sRec[64 * SR_STRIDE];        // 17 KB record staging

    const int tid = threadIdx.x;
    const int w = tid >> 5;          // warp 0..3
    const int lane = tid & 31;
    const int g = lane >> 2;         // 0..7
    const int tig = lane & 3;        // 0..3

    if (blockIdx.x == 0 && tid == 0) {
        int is64 = 1;
        int m = n_edges < 16 ? n_edges : 16;
        for (int i = 0; i < m; i++) {
            long long v = src_probe[i];
            if (v < 0 || v >= (long long)n_nodes) { is64 = 0; break; }
        }
        g_idx_is64 = is64;
    }

    // Build B fragments for k-tile = w (validated mapping):
    //   b0=(k=2tig, n) b1=(k+1) b2=(k+8) b3=(k+9), n = nt*8+g
    {
        int k0 = w * 16 + 2 * tig;
#pragma unroll
        for (int nt = 0; nt < 8; nt++) {
            int n = nt * 8 + g;
            __half2 b01 = __floats2half2_rn(W1[k0 * 64 + n], W1[(k0 + 1) * 64 + n]);
            __half2 b23 = __floats2half2_rn(W1[(k0 + 8) * 64 + n], W1[(k0 + 9) * 64 + n]);
            Bf[w][nt][lane][0] = *(uint32_t*)&b01;
            Bf[w][nt][lane][1] = *(uint32_t*)&b23;
        }
    }

    const int n_tiles = (n_nodes + 63) >> 6;       // 782
    for (int t = blockIdx.x; t < n_tiles; t += gridDim.x) {
        const int base = t * 64;
        const int rows = min(64, n_nodes - base);

        __syncthreads();   // Bf ready / protect sA,sRec reuse

        // load feat tile, coalesced float4 -> fp16 sA
#pragma unroll
        for (int p = 0; p < 8; p++) {
            int flat = p * 128 + tid;              // 64 rows x 16 float4
            int node = flat >> 4;
            int c = flat & 15;
            float4 f;
            if (node < rows) f = __ldg(&((const float4*)feat)[(long long)(base + node) * 16 + c]);
            else             f = make_float4(0.f, 0.f, 0.f, 0.f);
            __half2 h01 = __floats2half2_rn(f.x, f.y);
            __half2 h23 = __floats2half2_rn(f.z, f.w);
            __half* dstp = &sA[node * SA_STRIDE + c * 4];
            *(__half2*)(dstp)     = h01;
            *(__half2*)(dstp + 2) = h23;
        }
        __syncthreads();

        // MMA: warp w computes rows w*16 .. w*16+15
        {
            int r0 = w * 16 + g;
            int r1 = r0 + 8;
            uint32_t a[4][4];
#pragma unroll
            for (int kt = 0; kt < 4; kt++) {
                int col = kt * 16 + 2 * tig;
                a[kt][0] = *(uint32_t*)&sA[r0 * SA_STRIDE + col];
                a[kt][1] = *(uint32_t*)&sA[r1 * SA_STRIDE + col];
                a[kt][2] = *(uint32_t*)&sA[r0 * SA_STRIDE + col + 8];
                a[kt][3] = *(uint32_t*)&sA[r1 * SA_STRIDE + col + 8];
            }
#pragma unroll
            for (int nt = 0; nt < 8; nt++) {
                float d0 = 0.f, d1 = 0.f, d2 = 0.f, d3 = 0.f;
#pragma unroll
                for (int kt = 0; kt < 4; kt++) {
                    asm volatile(
                        "mma.sync.aligned.m16n8k16.row.col.f32.f16.f16.f32 "
                        "{%0,%1,%2,%3}, {%4,%5,%6,%7}, {%8,%9}, {%0,%1,%2,%3};"
                        : "+f"(d0), "+f"(d1), "+f"(d2), "+f"(d3)
                        : "r"(a[kt][0]), "r"(a[kt][1]), "r"(a[kt][2]), "r"(a[kt][3]),
                          "r"(Bf[kt][nt][lane][0]), "r"(Bf[kt][nt][lane][1]));
                }
                int cc = nt * 8 + 2 * tig;
                *(__half2*)&sRec[r0 * SR_STRIDE + cc] = __floats2half2_rn(d0, d1);
                *(__half2*)&sRec[r1 * SR_STRIDE + cc] = __floats2half2_rn(d2, d3);
            }
        }

        // permuted F half: smem -> smem (thread: node=tid/2, hf=tid&1)
        {
            int node = tid >> 1;
            int hf = tid & 1;
            const __half* srow = &sA[node * SA_STRIDE + (hf ? 32 : 0)];
            __half* drow = &sRec[node * SR_STRIDE + 64 + (hf ? 4 : 0)];
#pragma unroll
            for (int q = 0; q < 8; q++) {
                __half2 v0 = *(const __half2*)&srow[4 * q];
                __half2 v1 = *(const __half2*)&srow[4 * q + 2];
                *(__half2*)&drow[8 * q]     = v0;
                *(__half2*)&drow[8 * q + 2] = v1;
            }
        }
        __syncthreads();

        // flush sRec -> g_rec, coalesced uint4 (full 128B lines)
#pragma unroll
        for (int p = 0; p < 8; p++) {
            int flat = p * 128 + tid;
            int node = flat >> 4;
            int c = flat & 15;
            if (node < rows) {
                uint4 v = *(const uint4*)&sRec[node * SR_STRIDE + c * 8];
                ((uint4*)g_rec)[(long long)(base + node) * 16 + c] = v;
            }
        }
    }
}

// ---------------------------------------------------------------------------
// Edge kernel (exact R9 champion — at the LTS roofline):
// 8 lanes/edge, 2 edges/iteration, fp32 h math, direct coalesced STG.
// Grid = 1216 = 2 exact waves of 608 resident blocks (152 SMs x 4).
// ---------------------------------------------------------------------------
__global__ void __launch_bounds__(256, 4)
edge_kernel(const void* __restrict__ src_idx,
            const void* __restrict__ dst_idx,
            const float* __restrict__ b1,
            const float* __restrict__ W2,
            const float* __restrict__ b2,
            float* __restrict__ out,
            int n_edges) {
    const int l = threadIdx.x & 7;
    const int groupInBlock = threadIdx.x >> 3;
    const int gid = (int)blockIdx.x * 32 + groupInBlock;
    const int totalGroups = (int)gridDim.x * 32;

    const float4* B14 = (const float4*)b1;
    const float4* W24 = (const float4*)W2;
    float4 b1a = __ldg(&B14[2 * l]);
    float4 b1b = __ldg(&B14[2 * l + 1]);
    float4 w2a = __ldg(&W24[2 * l]);
    float4 w2b = __ldg(&W24[2 * l + 1]);
    float b2v = __ldg(&b2[0]);
    const int is64 = g_idx_is64;

    const uint4* R16 = (const uint4*)g_rec;
    float4* O4 = (float4*)out;

    for (int e0 = 2 * gid; e0 < n_edges; e0 += 2 * totalGroups) {
        int e1 = e0 + 1;
        bool hasB = (e1 < n_edges);

        long long sA, dA, sB = 0, dB = 0;
        if (is64) {
            longlong2 sp = __ldg(&((const longlong2*)src_idx)[e0 >> 1]);
            longlong2 dp = __ldg(&((const longlong2*)dst_idx)[e0 >> 1]);
            sA = sp.x; dA = dp.x; sB = sp.y; dB = dp.y;
        } else {
            int2 sp = __ldg(&((const int2*)src_idx)[e0 >> 1]);
            int2 dp = __ldg(&((const int2*)dst_idx)[e0 >> 1]);
            sA = sp.x; dA = dp.x; sB = sp.y; dB = dp.y;
        }

        uint4 gsA = __ldg(&R16[sA * 16 + l]);
        uint4 gdA = __ldg(&R16[dA * 16 + l]);
        uint4 fdA = __ldg(&R16[dA * 16 + 8 + l]);
        uint4 gsB, gdB, fdB;
        if (hasB) {
            gsB = __ldg(&R16[sB * 16 + l]);
            gdB = __ldg(&R16[dB * 16 + l]);
            fdB = __ldg(&R16[dB * 16 + 8 + l]);
        }

#define EDGE_BODY(GS, GD, FD, EIDX)                                            \
        {                                                                      \
            float2 s0 = __half22float2(*(const __half2*)&GS.x);                \
            float2 s1 = __half22float2(*(const __half2*)&GS.y);                \
            float2 s2 = __half22float2(*(const __half2*)&GS.z);                \
            float2 s3 = __half22float2(*(const __half2*)&GS.w);                \
            float2 dd0 = __half22float2(*(const __half2*)&GD.x);               \
            float2 dd1 = __half22float2(*(const __half2*)&GD.y);               \
            float2 dd2 = __half22float2(*(const __half2*)&GD.z);               \
            float2 dd3 = __half22float2(*(const __half2*)&GD.w);               \
            float h0 = fmaxf(s0.x - dd0.x + b1a.x, 0.f);                       \
            float h1 = fmaxf(s0.y - dd0.y + b1a.y, 0.f);                       \
            float h2 = fmaxf(s1.x - dd1.x + b1a.z, 0.f);                       \
            float h3 = fmaxf(s1.y - dd1.y + b1a.w, 0.f);                       \
            float h4 = fmaxf(s2.x - dd2.x + b1b.x, 0.f);                       \
            float h5 = fmaxf(s2.y - dd2.y + b1b.y, 0.f);                       \
            float h6 = fmaxf(s3.x - dd3.x + b1b.z, 0.f);                       \
            float h7 = fmaxf(s3.y - dd3.y + b1b.w, 0.f);                       \
            float p = h0 * w2a.x;                                              \
            p = fmaf(h1, w2a.y, p); p = fmaf(h2, w2a.z, p);                    \
            p = fmaf(h3, w2a.w, p); p = fmaf(h4, w2b.x, p);                    \
            p = fmaf(h5, w2b.y, p); p = fmaf(h6, w2b.z, p);                    \
            p = fmaf(h7, w2b.w, p);                                            \
            p += __shfl_xor_sync(0xffffffffu, p, 1, 8);                        \
            p += __shfl_xor_sync(0xffffffffu, p, 2, 8);                        \
            p += __shfl_xor_sync(0xffffffffu, p, 4, 8);                        \
            float aa = __expf(-fmaxf(p + b2v, 0.f));                           \
            float2 f0 = __half22float2(*(const __half2*)&FD.x);                \
            float2 f1 = __half22float2(*(const __half2*)&FD.y);                \
            float2 f2 = __half22float2(*(const __half2*)&FD.z);                \
            float2 f3 = __half22float2(*(const __half2*)&FD.w);                \
            float4 oA = make_float4(aa * f0.x, aa * f0.y, aa * f1.x, aa * f1.y); \
            float4 oB = make_float4(aa * f2.x, aa * f2.y, aa * f3.x, aa * f3.y); \
            long long ob = (long long)(EIDX) * 16;                             \
            O4[ob + l] = oA;                                                   \
            O4[ob + l + 8] = oB;                                               \
        }

        EDGE_BODY(gsA, gdA, fdA, e0)
        if (hasB) EDGE_BODY(gsB, gdB, fdB, e1)
#undef EDGE_BODY
    }
}

// ---------------------------------------------------------------------------
// kernel_launch — inputs (metadata order):
//   0 features [50000,64] f32
//   1 src_idx  [800000]   int64 (or int32, detected)
//   2 dst_idx  [800000]   int64/int32
//   3 W1 [64,64] f32   4 b1 [64] f32   5 W2 [64,1] f32   6 b2 [1] f32
// output: [800000, 64] f32
// ---------------------------------------------------------------------------
extern "C" void kernel_launch(void* const* d_in, const int* in_sizes, int n_in,
                              void* d_out, int out_size) {
    const float* feat = (const float*)d_in[0];
    const void*  src  = d_in[1];
    const void*  dst  = d_in[2];
    const float* W1   = (const float*)d_in[3];
    const float* b1   = (const float*)d_in[4];
    const float* W2   = (const float*)d_in[5];
    const float* b2   = (const float*)d_in[6];
    float* out = (float*)d_out;

    int n_nodes = in_sizes[0] / D;
    int n_edges = in_sizes[1];

    int n_tiles = (n_nodes + 63) / 64;           // 782
    node_gemm_kernel<<<n_tiles, 128>>>(feat, W1, n_nodes,
                                       (const long long*)src, n_edges);

    edge_kernel<<<1216, 256>>>(src, dst, b1, W2, b2, out, n_edges);
}

// round 17
// speedup vs baseline: 1.0702x; 1.0067x over previous
#include <cuda_runtime.h>
#include <cuda_fp16.h>
#include <cuda_bf16.h>
#include <cstdint>

#define N_NODES_MAX 50000
#define D 64

// Per-node record, 256 B:
//   halves [0..63]   = G = feat@W1 (fp16), natural column order
//   halves [64..127] = feat (fp16), PERMUTED: pos 64+8q+j holds
//                      feat[4q+j] for j<4, feat[32+4q+(j-4)] for j>=4
// Edge-lane l reads G cols [8l..8l+8) and its 8 feat cols each as ONE uint4.
__device__ __half g_rec[N_NODES_MAX * 128];
__device__ int g_idx_is64;

#define SA_STRIDE 66    // halves; conflict-free A frags
#define SR_STRIDE 136   // halves; conflict-free D writes, 16B-aligned flush

// 128-bit non-coherent load with L1 evict-last policy (keep g_rec hot in L1).
__device__ __forceinline__ uint4 ldg_el(const uint4* p) {
    uint4 v;
    asm volatile("ld.global.nc.L1::evict_last.v4.u32 {%0,%1,%2,%3}, [%4];"
                 : "=r"(v.x), "=r"(v.y), "=r"(v.z), "=r"(v.w) : "l"(p));
    return v;
}

// ---------------------------------------------------------------------------
// Node GEMM via tensor cores, fully smem-staged (champion config):
//   - 64-node tile of feat loaded ONCE, coalesced, converted to fp16 in sA
//   - m16n8k16 HMMA per warp (4 warps), D frags into padded sRec
//   - permuted F half built smem->smem from sA
//   - sRec flushed to g_rec with coalesced uint4 stores (full 128B lines)
// ---------------------------------------------------------------------------
__global__ void __launch_bounds__(128)
node_gemm_kernel(const float* __restrict__ feat,
                 const float* __restrict__ W1,
                 int n_nodes,
                 const long long* __restrict__ src_probe,
                 int n_edges) {
    __shared__ uint32_t Bf[4][8][32][2];           // 8 KB B fragments
    __shared__ __half sA[64 * SA_STRIDE];          // 8.25 KB fp16 feat tile
    __shared__ __half sRec[64 * SR_STRIDE];        // 17 KB record staging

    const int tid = threadIdx.x;
    const int w = tid >> 5;          // warp 0..3
    const int lane = tid & 31;
    const int g = lane >> 2;         // 0..7
    const int tig = lane & 3;        // 0..3

    if (blockIdx.x == 0 && tid == 0) {
        int is64 = 1;
        int m = n_edges < 16 ? n_edges : 16;
        for (int i = 0; i < m; i++) {
            long long v = src_probe[i];
            if (v < 0 || v >= (long long)n_nodes) { is64 = 0; break; }
        }
        g_idx_is64 = is64;
    }

    // Build B fragments for k-tile = w (validated mapping):
    //   b0=(k=2tig, n) b1=(k+1) b2=(k+8) b3=(k+9), n = nt*8+g
    {
        int k0 = w * 16 + 2 * tig;
#pragma unroll
        for (int nt = 0; nt < 8; nt++) {
            int n = nt * 8 + g;
            __half2 b01 = __floats2half2_rn(W1[k0 * 64 + n], W1[(k0 + 1) * 64 + n]);
            __half2 b23 = __floats2half2_rn(W1[(k0 + 8) * 64 + n], W1[(k0 + 9) * 64 + n]);
            Bf[w][nt][lane][0] = *(uint32_t*)&b01;
            Bf[w][nt][lane][1] = *(uint32_t*)&b23;
        }
    }

    const int n_tiles = (n_nodes + 63) >> 6;       // 782
    for (int t = blockIdx.x; t < n_tiles; t += gridDim.x) {
        const int base = t * 64;
        const int rows = min(64, n_nodes - base);

        __syncthreads();   // Bf ready / protect sA,sRec reuse

        // load feat tile, coalesced float4 -> fp16 sA
#pragma unroll
        for (int p = 0; p < 8; p++) {
            int flat = p * 128 + tid;              // 64 rows x 16 float4
            int node = flat >> 4;
            int c = flat & 15;
            float4 f;
            if (node < rows) f = __ldg(&((const float4*)feat)[(long long)(base + node) * 16 + c]);
            else             f = make_float4(0.f, 0.f, 0.f, 0.f);
            __half2 h01 = __floats2half2_rn(f.x, f.y);
            __half2 h23 = __floats2half2_rn(f.z, f.w);
            __half* dstp = &sA[node * SA_STRIDE + c * 4];
            *(__half2*)(dstp)     = h01;
            *(__half2*)(dstp + 2) = h23;
        }
        __syncthreads();

        // MMA: warp w computes rows w*16 .. w*16+15
        {
            int r0 = w * 16 + g;
            int r1 = r0 + 8;
            uint32_t a[4][4];
#pragma unroll
            for (int kt = 0; kt < 4; kt++) {
                int col = kt * 16 + 2 * tig;
                a[kt][0] = *(uint32_t*)&sA[r0 * SA_STRIDE + col];
                a[kt][1] = *(uint32_t*)&sA[r1 * SA_STRIDE + col];
                a[kt][2] = *(uint32_t*)&sA[r0 * SA_STRIDE + col + 8];
                a[kt][3] = *(uint32_t*)&sA[r1 * SA_STRIDE + col + 8];
            }
#pragma unroll
            for (int nt = 0; nt < 8; nt++) {
                float d0 = 0.f, d1 = 0.f, d2 = 0.f, d3 = 0.f;
#pragma unroll
                for (int kt = 0; kt < 4; kt++) {
                    asm volatile(
                        "mma.sync.aligned.m16n8k16.row.col.f32.f16.f16.f32 "
                        "{%0,%1,%2,%3}, {%4,%5,%6,%7}, {%8,%9}, {%0,%1,%2,%3};"
                        : "+f"(d0), "+f"(d1), "+f"(d2), "+f"(d3)
                        : "r"(a[kt][0]), "r"(a[kt][1]), "r"(a[kt][2]), "r"(a[kt][3]),
                          "r"(Bf[kt][nt][lane][0]), "r"(Bf[kt][nt][lane][1]));
                }
                int cc = nt * 8 + 2 * tig;
                *(__half2*)&sRec[r0 * SR_STRIDE + cc] = __floats2half2_rn(d0, d1);
                *(__half2*)&sRec[r1 * SR_STRIDE + cc] = __floats2half2_rn(d2, d3);
            }
        }

        // permuted F half: smem -> smem (thread: node=tid/2, hf=tid&1)
        {
            int node = tid >> 1;
            int hf = tid & 1;
            const __half* srow = &sA[node * SA_STRIDE + (hf ? 32 : 0)];
            __half* drow = &sRec[node * SR_STRIDE + 64 + (hf ? 4 : 0)];
#pragma unroll
            for (int q = 0; q < 8; q++) {
                __half2 v0 = *(const __half2*)&srow[4 * q];
                __half2 v1 = *(const __half2*)&srow[4 * q + 2];
                *(__half2*)&drow[8 * q]     = v0;
                *(__half2*)&drow[8 * q + 2] = v1;
            }
        }
        __syncthreads();

        // flush sRec -> g_rec, coalesced uint4 (full 128B lines)
#pragma unroll
        for (int p = 0; p < 8; p++) {
            int flat = p * 128 + tid;
            int node = flat >> 4;
            int c = flat & 15;
            if (node < rows) {
                uint4 v = *(const uint4*)&sRec[node * SR_STRIDE + c * 8];
                ((uint4*)g_rec)[(long long)(base + node) * 16 + c] = v;
            }
        }
    }
}

// ---------------------------------------------------------------------------
// Edge kernel (champion structure, at the LTS roofline):
// 8 lanes/edge, 2 edges/iteration, fp32 h math, direct coalesced STG.
// Record gathers use L1::evict_last — edge kernel has zero smem, so the
// full 228 KB/SM L1 acts as a g_rec cache (12.8 MB vs 34 MB aggregate L1).
// Grid = 1216 = 2 exact waves of 608 resident blocks (152 SMs x 4).
// ---------------------------------------------------------------------------
__global__ void __launch_bounds__(256, 4)
edge_kernel(const void* __restrict__ src_idx,
            const void* __restrict__ dst_idx,
            const float* __restrict__ b1,
            const float* __restrict__ W2,
            const float* __restrict__ b2,
            float* __restrict__ out,
            int n_edges) {
    const int l = threadIdx.x & 7;
    const int groupInBlock = threadIdx.x >> 3;
    const int gid = (int)blockIdx.x * 32 + groupInBlock;
    const int totalGroups = (int)gridDim.x * 32;

    const float4* B14 = (const float4*)b1;
    const float4* W24 = (const float4*)W2;
    float4 b1a = __ldg(&B14[2 * l]);
    float4 b1b = __ldg(&B14[2 * l + 1]);
    float4 w2a = __ldg(&W24[2 * l]);
    float4 w2b = __ldg(&W24[2 * l + 1]);
    float b2v = __ldg(&b2[0]);
    const int is64 = g_idx_is64;

    const uint4* R16 = (const uint4*)g_rec;
    float4* O4 = (float4*)out;

    for (int e0 = 2 * gid; e0 < n_edges; e0 += 2 * totalGroups) {
        int e1 = e0 + 1;
        bool hasB = (e1 < n_edges);

        long long sA, dA, sB = 0, dB = 0;
        if (is64) {
            longlong2 sp = __ldg(&((const longlong2*)src_idx)[e0 >> 1]);
            longlong2 dp = __ldg(&((const longlong2*)dst_idx)[e0 >> 1]);
            sA = sp.x; dA = dp.x; sB = sp.y; dB = dp.y;
        } else {
            int2 sp = __ldg(&((const int2*)src_idx)[e0 >> 1]);
            int2 dp = __ldg(&((const int2*)dst_idx)[e0 >> 1]);
            sA = sp.x; dA = dp.x; sB = sp.y; dB = dp.y;
        }

        uint4 gsA = ldg_el(&R16[sA * 16 + l]);
        uint4 gdA = ldg_el(&R16[dA * 16 + l]);
        uint4 fdA = ldg_el(&R16[dA * 16 + 8 + l]);
        uint4 gsB, gdB, fdB;
        if (hasB) {
            gsB = ldg_el(&R16[sB * 16 + l]);
            gdB = ldg_el(&R16[dB * 16 + l]);
            fdB = ldg_el(&R16[dB * 16 + 8 + l]);
        }

#define EDGE_BODY(GS, GD, FD, EIDX)                                            \
        {                                                                      \
            float2 s0 = __half22float2(*(const __half2*)&GS.x);                \
            float2 s1 = __half22float2(*(const __half2*)&GS.y);                \
            float2 s2 = __half22float2(*(const __half2*)&GS.z);                \
            float2 s3 = __half22float2(*(const __half2*)&GS.w);                \
            float2 dd0 = __half22float2(*(const __half2*)&GD.x);               \
            float2 dd1 = __half22float2(*(const __half2*)&GD.y);               \
            float2 dd2 = __half22float2(*(const __half2*)&GD.z);               \
            float2 dd3 = __half22float2(*(const __half2*)&GD.w);               \
            float h0 = fmaxf(s0.x - dd0.x + b1a.x, 0.f);                       \
            float h1 = fmaxf(s0.y - dd0.y + b1a.y, 0.f);                       \
            float h2 = fmaxf(s1.x - dd1.x + b1a.z, 0.f);                       \
            float h3 = fmaxf(s1.y - dd1.y + b1a.w, 0.f);                       \
            float h4 = fmaxf(s2.x - dd2.x + b1b.x, 0.f);                       \
            float h5 = fmaxf(s2.y - dd2.y + b1b.y, 0.f);                       \
            float h6 = fmaxf(s3.x - dd3.x + b1b.z, 0.f);                       \
            float h7 = fmaxf(s3.y - dd3.y + b1b.w, 0.f);                       \
            float p = h0 * w2a.x;                                              \
            p = fmaf(h1, w2a.y, p); p = fmaf(h2, w2a.z, p);                    \
            p = fmaf(h3, w2a.w, p); p = fmaf(h4, w2b.x, p);                    \
            p = fmaf(h5, w2b.y, p); p = fmaf(h6, w2b.z, p);                    \
            p = fmaf(h7, w2b.w, p);                                            \
            p += __shfl_xor_sync(0xffffffffu, p, 1, 8);                        \
            p += __shfl_xor_sync(0xffffffffu, p, 2, 8);                        \
            p += __shfl_xor_sync(0xffffffffu, p, 4, 8);                        \
            float aa = __expf(-fmaxf(p + b2v, 0.f));                           \
            float2 f0 = __half22float2(*(const __half2*)&FD.x);                \
            float2 f1 = __half22float2(*(const __half2*)&FD.y);                \
            float2 f2 = __half22float2(*(const __half2*)&FD.z);                \
            float2 f3 = __half22float2(*(const __half2*)&FD.w);                \
            float4 oA = make_float4(aa * f0.x, aa * f0.y, aa * f1.x, aa * f1.y); \
            float4 oB = make_float4(aa * f2.x, aa * f2.y, aa * f3.x, aa * f3.y); \
            long long ob = (long long)(EIDX) * 16;                             \
            O4[ob + l] = oA;                                                   \
            O4[ob + l + 8] = oB;                                               \
        }

        EDGE_BODY(gsA, gdA, fdA, e0)
        if (hasB) EDGE_BODY(gsB, gdB, fdB, e1)
#undef EDGE_BODY
    }
}

// ---------------------------------------------------------------------------
// kernel_launch — inputs (metadata order):
//   0 features [50000,64] f32
//   1 src_idx  [800000]   int64 (or int32, detected)
//   2 dst_idx  [800000]   int64/int32
//   3 W1 [64,64] f32   4 b1 [64] f32   5 W2 [64,1] f32   6 b2 [1] f32
// output: [800000, 64] f32
// ---------------------------------------------------------------------------
extern "C" void kernel_launch(void* const* d_in, const int* in_sizes, int n_in,
                              void* d_out, int out_size) {
    const float* feat = (const float*)d_in[0];
    const void*  src  = d_in[1];
    const void*  dst  = d_in[2];
    const float* W1   = (const float*)d_in[3];
    const float* b1   = (const float*)d_in[4];
    const float* W2   = (const float*)d_in[5];
    const float* b2   = (const float*)d_in[6];
    float* out = (float*)d_out;

    int n_nodes = in_sizes[0] / D;
    int n_edges = in_sizes[1];

    int n_tiles = (n_nodes + 63) / 64;           // 782
    node_gemm_kernel<<<n_tiles, 128>>>(feat, W1, n_nodes,
                                       (const long long*)src, n_edges);

    edge_kernel<<<1216, 256>>>(src, dst, b1, W2, b2, out, n_edges);
}